// round 9
// baseline (speedup 1.0000x reference)
#include <cuda_runtime.h>
#include <cuda_fp16.h>
#include <cstdint>

// Problem dims
#define NB 4
#define NT 512
#define NU 128
#define ND 512
#define NV 1024

#define NSUB 128              // N columns per n-iteration
#define NITERS (NV / NSUB)    // 8
#define KC 64                 // K chunk
#define NCH (ND / KC)         // 8
#define GTOT (NITERS * NCH)   // 64 flattened chunks
#define NSTAGE 4
#define NTHREADS 512

// SMEM layout (dynamic)
#define OFF_SRC  0                      // 512 f32 = 2048B
#define OFF_BIAS 2048                   // 1024 f32 = 4096B
#define OFF_MBAR 6144                   // 4 mbarriers (8B each)
#define OFF_A    8192                   // 128 x 512 f16 = 131072B (row stride 1024B)
#define OFF_B    (8192 + 131072)        // 4 x 16384B TMA-filled stages
#define BBUF     16384
#define SMEM_TOTAL (OFF_B + NSTAGE * BBUF)   // 204800

// Swizzles: xor bits [4:6] of the k-byte offset with low 3 row bits.
#define ASW(row, kbyte) ((uint32_t)((row) * 1024u + ((uint32_t)(kbyte) ^ (((uint32_t)(row) & 7u) << 4))))
#define BSW(n, kbyte)   ((uint32_t)((n) * 128u  + ((uint32_t)(kbyte) ^ (((uint32_t)(n) & 7u) << 4))))

// W repacked to f16, tiled + pre-swizzled: 64 tiles of 16KB; tile g=(ni*8+c)
// holds n-subtile ni (128 rows), k-chunk c (64 cols), inner layout = BSW.
static __device__ __half g_Wtiled[NV * ND];

__device__ __forceinline__ uint32_t smem_u32(const void* p) {
    uint32_t a;
    asm("{ .reg .u64 t; cvta.to.shared.u64 t, %1; cvt.u32.u64 %0, t; }" : "=r"(a) : "l"(p));
    return a;
}

// ---- TMA bulk copy + mbarrier (sm_90 baseline PTX, valid at .target sm_103) ----
__device__ __forceinline__ void bulk_g2s(uint32_t dst, const void* src, uint32_t bytes,
                                         uint32_t mbar) {
    asm volatile(
        "cp.async.bulk.shared::cluster.global.mbarrier::complete_tx::bytes [%0], [%1], %2, [%3];"
        :: "r"(dst), "l"(src), "r"(bytes), "r"(mbar) : "memory");
}
#define MB_INIT(addr, cnt) \
    asm volatile("mbarrier.init.shared.b64 [%0], %1;" :: "r"(addr), "r"((uint32_t)(cnt)) : "memory")
#define MB_EXPECT(addr, bytes) \
    asm volatile("mbarrier.arrive.expect_tx.shared.b64 _, [%0], %1;" \
                 :: "r"(addr), "r"((uint32_t)(bytes)) : "memory")
#define MB_WAIT(addr, ph) do {                                                                   \
    uint32_t _a = (addr), _p = (uint32_t)(ph), _d;                                               \
    asm volatile("{\n .reg .pred P;\n"                                                           \
        " mbarrier.try_wait.parity.acquire.cta.shared::cta.b64 P, [%1], %2;\n"                   \
        " selp.b32 %0,1,0,P;\n}" : "=r"(_d) : "r"(_a), "r"(_p) : "memory");                      \
    while (!_d) {                                                                                \
        asm volatile("{\n .reg .pred P;\n"                                                       \
            " mbarrier.try_wait.parity.acquire.cta.shared::cta.b64 P, [%1], %2, 0x989680;\n"     \
            " selp.b32 %0,1,0,P;\n}" : "=r"(_d) : "r"(_a), "r"(_p) : "memory");                  \
    }                                                                                            \
} while (0)

__device__ __forceinline__ void ldmatrix_x4(uint32_t& r0, uint32_t& r1, uint32_t& r2,
                                            uint32_t& r3, uint32_t addr) {
    asm volatile("ldmatrix.sync.aligned.m8n8.x4.shared.b16 {%0,%1,%2,%3}, [%4];"
                 : "=r"(r0), "=r"(r1), "=r"(r2), "=r"(r3) : "r"(addr));
}

// f16-accumulate HMMA: D,C are 2x b32 (half2 pairs).
__device__ __forceinline__ void mma_16816_f16(uint32_t& c0, uint32_t& c1,
                                              uint32_t a0, uint32_t a1, uint32_t a2, uint32_t a3,
                                              uint32_t b0, uint32_t b1) {
    asm volatile("mma.sync.aligned.m16n8k16.row.col.f16.f16.f16.f16 "
                 "{%0,%1}, {%2,%3,%4,%5}, {%6,%7}, {%0,%1};"
                 : "+r"(c0), "+r"(c1)
                 : "r"(a0), "r"(a1), "r"(a2), "r"(a3), "r"(b0), "r"(b1));
}

// tanh-formula gelu via MUFU.TANH (proven 3.3e-4 rel_err)
__device__ __forceinline__ float gelu_fast(float x) {
    float u = x * (0.7978845608028654f + 0.035677408136300125f * x * x);
    float th;
    asm("tanh.approx.f32 %0, %1;" : "=f"(th) : "f"(u));
    float hx = 0.5f * x;
    return fmaf(hx, th, hx);
}

// ---------------------------------------------------------------------------
// Kernel 1: convert W (fp32, V x D) into tiled + pre-swizzled f16 layout.
__global__ void wconv_kernel(const float* __restrict__ W) {
    int idx = blockIdx.x * 256 + threadIdx.x;   // 0..65535
    int tile = idx >> 10;                        // 0..63
    int rem = idx & 1023;
    int nl = rem >> 3;                           // 0..127 (n within subtile)
    int k16 = rem & 7;                           // 16B unit within 128B row
    int v = (tile >> 3) * NSUB + nl;
    int k = (tile & 7) * KC + k16 * 8;
    const float* p = W + (size_t)v * ND + k;
    float4 x0 = *reinterpret_cast<const float4*>(p);
    float4 x1 = *reinterpret_cast<const float4*>(p + 4);
    __half2 h0 = __floats2half2_rn(x0.x, x0.y);
    __half2 h1 = __floats2half2_rn(x0.z, x0.w);
    __half2 h2 = __floats2half2_rn(x1.x, x1.y);
    __half2 h3 = __floats2half2_rn(x1.z, x1.w);
    uint4 o;
    o.x = *reinterpret_cast<uint32_t*>(&h0);
    o.y = *reinterpret_cast<uint32_t*>(&h1);
    o.z = *reinterpret_cast<uint32_t*>(&h2);
    o.w = *reinterpret_cast<uint32_t*>(&h3);
    uint32_t off = (uint32_t)tile * BBUF + BSW(nl, k16 * 16);
    *reinterpret_cast<uint4*>(reinterpret_cast<char*>(g_Wtiled) + off) = o;
}

// ---------------------------------------------------------------------------
// Kernel 2: fused gelu + GEMM. TMA bulk W-streaming (no LSU leg) + f16-acc
// HMMA (potential 2x tensor leg) flushed to fp32 masters every K=128.
__global__ __launch_bounds__(NTHREADS, 1)
void joiner_kernel(const float* __restrict__ src, const float* __restrict__ tgt,
                   const float* __restrict__ bias, float* __restrict__ out) {
    extern __shared__ char smem[];
    const uint32_t sb = smem_u32(smem);
    const int tid = threadIdx.x;
    const int wid = tid >> 5;
    const int lid = tid & 31;
    const int t = blockIdx.x;
    const int b = blockIdx.y;

    float* src_s = reinterpret_cast<float*>(smem + OFF_SRC);
    float* bias_s = reinterpret_cast<float*>(smem + OFF_BIAS);
    src_s[tid] = src[(size_t)(b * NT + t) * ND + tid];
    bias_s[tid] = bias[tid];
    bias_s[tid + 512] = bias[tid + 512];

    if (tid == 0) {
#pragma unroll
        for (int s = 0; s < NSTAGE; ++s) MB_INIT(sb + OFF_MBAR + s * 8, 1);
        asm volatile("fence.mbarrier_init.release.cluster;" ::: "memory");
    }
    __syncthreads();   // src_s ready + mbarriers initialized

    // Kick off the first 4 W-tile bulk copies; they overlap the gelu below.
    if (tid == 0) {
#pragma unroll
        for (int g0 = 0; g0 < NSTAGE; ++g0) {
            MB_EXPECT(sb + OFF_MBAR + g0 * 8, BBUF);
            bulk_g2s(sb + OFF_B + g0 * BBUF,
                     reinterpret_cast<const char*>(g_Wtiled) + (size_t)g0 * BBUF,
                     BBUF, sb + OFF_MBAR + g0 * 8);
        }
    }

    // --- A tile: gelu(src + tgt) -> f16 in swizzled SMEM ---
    {
        const int arow = tid >> 2;
        const int aq = tid & 3;
        const float* trow = tgt + (size_t)(b * NU + arow) * ND + aq * 128;
        const float* srow = src_s + aq * 128;
#pragma unroll
        for (int cc = 0; cc < 128; cc += 8) {
            float4 v0 = *reinterpret_cast<const float4*>(trow + cc);
            float4 v1 = *reinterpret_cast<const float4*>(trow + cc + 4);
            float4 s0 = *reinterpret_cast<const float4*>(srow + cc);
            float4 s1 = *reinterpret_cast<const float4*>(srow + cc + 4);
            __half2 h0 = __floats2half2_rn(gelu_fast(v0.x + s0.x), gelu_fast(v0.y + s0.y));
            __half2 h1 = __floats2half2_rn(gelu_fast(v0.z + s0.z), gelu_fast(v0.w + s0.w));
            __half2 h2 = __floats2half2_rn(gelu_fast(v1.x + s1.x), gelu_fast(v1.y + s1.y));
            __half2 h3 = __floats2half2_rn(gelu_fast(v1.z + s1.z), gelu_fast(v1.w + s1.w));
            uint4 pk;
            pk.x = *reinterpret_cast<uint32_t*>(&h0);
            pk.y = *reinterpret_cast<uint32_t*>(&h1);
            pk.z = *reinterpret_cast<uint32_t*>(&h2);
            pk.w = *reinterpret_cast<uint32_t*>(&h3);
            uint32_t kbyte = (uint32_t)(aq * 128 + cc) * 2;
            *reinterpret_cast<uint4*>(smem + OFF_A + ASW(arow, kbyte)) = pk;
        }
    }
    __syncthreads();   // A tile ready

    // warp tiling: 4 (m) x 4 (n) warps of 32x32 tiles
    const int wm = wid & 3;
    const int wn = wid >> 2;
    const int a_r = (lid & 7) + (((lid >> 3) & 1) << 3);
    const int a_kh = (lid >> 4);
    const int b_n = (lid & 7) + (((lid >> 4) & 1) << 3);
    const int b_kh = ((lid >> 3) & 1);

    float acc[2][4][4];           // fp32 masters
#pragma unroll
    for (int mt = 0; mt < 2; ++mt)
#pragma unroll
        for (int j = 0; j < 4; ++j)
#pragma unroll
            for (int q = 0; q < 4; ++q) acc[mt][j][q] = 0.0f;

    uint32_t hacc[2][4][2];       // f16 partials (half2 pairs)
#pragma unroll
    for (int mt = 0; mt < 2; ++mt)
#pragma unroll
        for (int j = 0; j < 4; ++j) { hacc[mt][j][0] = 0u; hacc[mt][j][1] = 0u; }

    const size_t rowbase = (size_t)((b * NT + t) * NU);

    for (int g = 0; g < GTOT; ++g) {
        const int s = g & 3;
        const int c = g & 7;

        // Wait for stage s fill of this round (phase flips each reuse).
        MB_WAIT(sb + OFF_MBAR + s * 8, (g >> 2) & 1);

        const uint32_t Bbase = sb + OFF_B + s * BBUF;
#pragma unroll
        for (int ks = 0; ks < 4; ++ks) {
            const int k0 = c * KC + ks * 16;
            const uint32_t kb_a = (uint32_t)(k0 + a_kh * 8) * 2;
            uint32_t a0[4], a1[4];
            {
                int r = wm * 32 + a_r;
                ldmatrix_x4(a0[0], a0[1], a0[2], a0[3], sb + OFF_A + ASW(r, kb_a));
                r += 16;
                ldmatrix_x4(a1[0], a1[1], a1[2], a1[3], sb + OFF_A + ASW(r, kb_a));
            }
            const uint32_t kb_b = (uint32_t)(ks * 16 + b_kh * 8) * 2;
            uint32_t bf[8];
            {
                int n = wn * 32 + b_n;
                ldmatrix_x4(bf[0], bf[1], bf[2], bf[3], Bbase + BSW(n, kb_b));
                n += 16;
                ldmatrix_x4(bf[4], bf[5], bf[6], bf[7], Bbase + BSW(n, kb_b));
            }
#pragma unroll
            for (int mt = 0; mt < 2; ++mt) {
                uint32_t* a = mt ? a1 : a0;
#pragma unroll
                for (int j = 0; j < 4; ++j) {
                    mma_16816_f16(hacc[mt][j][0], hacc[mt][j][1],
                                  a[0], a[1], a[2], a[3], bf[2 * j], bf[2 * j + 1]);
                }
            }
        }

        // Flush f16 partials (K=128 accumulated) into fp32 masters every 2 chunks.
        if (c & 1) {
#pragma unroll
            for (int mt = 0; mt < 2; ++mt)
#pragma unroll
                for (int j = 0; j < 4; ++j) {
                    float2 lo = __half22float2(*reinterpret_cast<__half2*>(&hacc[mt][j][0]));
                    float2 hi = __half22float2(*reinterpret_cast<__half2*>(&hacc[mt][j][1]));
                    acc[mt][j][0] += lo.x;
                    acc[mt][j][1] += lo.y;
                    acc[mt][j][2] += hi.x;
                    acc[mt][j][3] += hi.y;
                    hacc[mt][j][0] = 0u;
                    hacc[mt][j][1] = 0u;
                }
        }

        // End of an n-subtile: epilogue (overlaps other warps' MMAs) + acc reset.
        if (c == 7) {
            const int nbase = (g >> 3) * NSUB;
#pragma unroll
            for (int mt = 0; mt < 2; ++mt) {
                const int r = wm * 32 + mt * 16 + (lid >> 2);
#pragma unroll
                for (int j = 0; j < 4; ++j) {
                    const int col = nbase + wn * 32 + j * 8 + (lid & 3) * 2;
                    const float bi0 = bias_s[col], bi1 = bias_s[col + 1];
                    float2 o0, o1;
                    o0.x = acc[mt][j][0] + bi0;
                    o0.y = acc[mt][j][1] + bi1;
                    o1.x = acc[mt][j][2] + bi0;
                    o1.y = acc[mt][j][3] + bi1;
                    *reinterpret_cast<float2*>(out + (rowbase + r) * NV + col) = o0;
                    *reinterpret_cast<float2*>(out + (rowbase + r + 8) * NV + col) = o1;
                    acc[mt][j][0] = 0.0f; acc[mt][j][1] = 0.0f;
                    acc[mt][j][2] = 0.0f; acc[mt][j][3] = 0.0f;
                }
            }
        }

        // All warps done with stage s -> refill it with chunk g+4.
        __syncthreads();
        if (g + NSTAGE < GTOT && tid == 0) {
            MB_EXPECT(sb + OFF_MBAR + s * 8, BBUF);
            bulk_g2s(sb + OFF_B + s * BBUF,
                     reinterpret_cast<const char*>(g_Wtiled) + (size_t)(g + NSTAGE) * BBUF,
                     BBUF, sb + OFF_MBAR + s * 8);
        }
    }
}

// ---------------------------------------------------------------------------
// Kernel 3: length passthrough tail
__global__ void tail_kernel(const int* __restrict__ sl, const int* __restrict__ tl,
                            float* __restrict__ out, int extra) {
    int i = threadIdx.x;
    if (i < 4 && i < extra) out[i] = (float)sl[i];
    if (i >= 4 && i < 8 && i < extra) out[i] = (float)tl[i - 4];
}

// ---------------------------------------------------------------------------
extern "C" void kernel_launch(void* const* d_in, const int* in_sizes, int n_in,
                              void* d_out, int out_size) {
    const float* src  = (const float*)d_in[0];
    const int*   slen = (const int*)d_in[1];
    const float* tgt  = (const float*)d_in[2];
    const int*   tlen = (const int*)d_in[3];
    const float* W    = (const float*)d_in[4];
    const float* bias = (const float*)d_in[5];
    float* out = (float*)d_out;

    cudaFuncSetAttribute(joiner_kernel, cudaFuncAttributeMaxDynamicSharedMemorySize, SMEM_TOTAL);

    wconv_kernel<<<256, 256>>>(W);

    dim3 grid(NT, NB);  // 2048 CTAs, one per (b,t)
    joiner_kernel<<<grid, NTHREADS, SMEM_TOTAL>>>(src, tgt, bias, out);

    const long long main_elems = (long long)NB * NT * NU * NV;
    long long extra = (long long)out_size - main_elems;
    if (extra > 0) {
        tail_kernel<<<1, 32>>>(slen, tlen, out + main_elems, (int)extra);
    }
}

// round 13
// speedup vs baseline: 1.2176x; 1.2176x over previous
#include <cuda_runtime.h>
#include <cuda_fp16.h>
#include <cstdint>

// Problem dims
#define NB 4
#define NT 512
#define NU 128
#define ND 512
#define NV 1024

#define MTILE 64              // M rows per CTA (half of U)
#define NSUB 128              // N columns per n-iteration
#define NITERS (NV / NSUB)    // 8
#define KC 64                 // K chunk
#define NCH (ND / KC)         // 8
#define GTOT (NITERS * NCH)   // 64 flattened chunks
#define NSTAGE 2
#define NTHREADS 256

// SMEM layout (dynamic) — 104 KB/CTA so 2 CTAs fit per SM (228 KB)
#define OFF_SRC  0                      // 512 f32 = 2048B
#define OFF_BIAS 2048                   // 1024 f32 = 4096B
#define OFF_MBAR 6144                   // 2 mbarriers (8B each)
#define OFF_A    8192                   // 64 x 512 f16 = 65536B (row stride 1024B)
#define OFF_B    (8192 + 65536)         // 2 x 16384B TMA-filled stages
#define BBUF     16384
#define SMEM_TOTAL (OFF_B + NSTAGE * BBUF)   // 106496

// Swizzles: xor bits [4:6] of the k-byte offset with low 3 row bits.
#define ASW(row, kbyte) ((uint32_t)((row) * 1024u + ((uint32_t)(kbyte) ^ (((uint32_t)(row) & 7u) << 4))))
#define BSW(n, kbyte)   ((uint32_t)((n) * 128u  + ((uint32_t)(kbyte) ^ (((uint32_t)(n) & 7u) << 4))))

// W repacked to f16, tiled + pre-swizzled: 64 tiles of 16KB; tile g=(ni*8+c)
// holds n-subtile ni (128 rows), k-chunk c (64 cols), inner layout = BSW.
static __device__ __half g_Wtiled[NV * ND];

__device__ __forceinline__ uint32_t smem_u32(const void* p) {
    uint32_t a;
    asm("{ .reg .u64 t; cvta.to.shared.u64 t, %1; cvt.u32.u64 %0, t; }" : "=r"(a) : "l"(p));
    return a;
}

// ---- TMA bulk copy + mbarrier (sm_90 baseline PTX, valid at .target sm_103) ----
__device__ __forceinline__ void bulk_g2s(uint32_t dst, const void* src, uint32_t bytes,
                                         uint32_t mbar) {
    asm volatile(
        "cp.async.bulk.shared::cluster.global.mbarrier::complete_tx::bytes [%0], [%1], %2, [%3];"
        :: "r"(dst), "l"(src), "r"(bytes), "r"(mbar) : "memory");
}
#define MB_INIT(addr, cnt) \
    asm volatile("mbarrier.init.shared.b64 [%0], %1;" :: "r"(addr), "r"((uint32_t)(cnt)) : "memory")
#define MB_EXPECT(addr, bytes) \
    asm volatile("mbarrier.arrive.expect_tx.shared.b64 _, [%0], %1;" \
                 :: "r"(addr), "r"((uint32_t)(bytes)) : "memory")
#define MB_WAIT(addr, ph) do {                                                                   \
    uint32_t _a = (addr), _p = (uint32_t)(ph), _d;                                               \
    asm volatile("{\n .reg .pred P;\n"                                                           \
        " mbarrier.try_wait.parity.acquire.cta.shared::cta.b64 P, [%1], %2;\n"                   \
        " selp.b32 %0,1,0,P;\n}" : "=r"(_d) : "r"(_a), "r"(_p) : "memory");                      \
    while (!_d) {                                                                                \
        asm volatile("{\n .reg .pred P;\n"                                                       \
            " mbarrier.try_wait.parity.acquire.cta.shared::cta.b64 P, [%1], %2, 0x989680;\n"     \
            " selp.b32 %0,1,0,P;\n}" : "=r"(_d) : "r"(_a), "r"(_p) : "memory");                  \
    }                                                                                            \
} while (0)

__device__ __forceinline__ void ldmatrix_x4(uint32_t& r0, uint32_t& r1, uint32_t& r2,
                                            uint32_t& r3, uint32_t addr) {
    asm volatile("ldmatrix.sync.aligned.m8n8.x4.shared.b16 {%0,%1,%2,%3}, [%4];"
                 : "=r"(r0), "=r"(r1), "=r"(r2), "=r"(r3) : "r"(addr));
}

__device__ __forceinline__ void mma_16816(float& c0, float& c1, float& c2, float& c3,
                                          uint32_t a0, uint32_t a1, uint32_t a2, uint32_t a3,
                                          uint32_t b0, uint32_t b1) {
    asm volatile("mma.sync.aligned.m16n8k16.row.col.f32.f16.f16.f32 "
                 "{%0,%1,%2,%3}, {%4,%5,%6,%7}, {%8,%9}, {%0,%1,%2,%3};"
                 : "+f"(c0), "+f"(c1), "+f"(c2), "+f"(c3)
                 : "r"(a0), "r"(a1), "r"(a2), "r"(a3), "r"(b0), "r"(b1));
}

// tanh-formula gelu via MUFU.TANH (proven 3.3e-4 rel_err)
__device__ __forceinline__ float gelu_fast(float x) {
    float u = x * (0.7978845608028654f + 0.035677408136300125f * x * x);
    float th;
    asm("tanh.approx.f32 %0, %1;" : "=f"(th) : "f"(u));
    float hx = 0.5f * x;
    return fmaf(hx, th, hx);
}

// ---------------------------------------------------------------------------
// Kernel 1: convert W (fp32, V x D) into tiled + pre-swizzled f16 layout.
__global__ void wconv_kernel(const float* __restrict__ W) {
    int idx = blockIdx.x * 256 + threadIdx.x;   // 0..65535
    int tile = idx >> 10;                        // 0..63
    int rem = idx & 1023;
    int nl = rem >> 3;                           // 0..127 (n within subtile)
    int k16 = rem & 7;                           // 16B unit within 128B row
    int v = (tile >> 3) * NSUB + nl;
    int k = (tile & 7) * KC + k16 * 8;
    const float* p = W + (size_t)v * ND + k;
    float4 x0 = *reinterpret_cast<const float4*>(p);
    float4 x1 = *reinterpret_cast<const float4*>(p + 4);
    __half2 h0 = __floats2half2_rn(x0.x, x0.y);
    __half2 h1 = __floats2half2_rn(x0.z, x0.w);
    __half2 h2 = __floats2half2_rn(x1.x, x1.y);
    __half2 h3 = __floats2half2_rn(x1.z, x1.w);
    uint4 o;
    o.x = *reinterpret_cast<uint32_t*>(&h0);
    o.y = *reinterpret_cast<uint32_t*>(&h1);
    o.z = *reinterpret_cast<uint32_t*>(&h2);
    o.w = *reinterpret_cast<uint32_t*>(&h3);
    uint32_t off = (uint32_t)tile * BBUF + BSW(nl, k16 * 16);
    *reinterpret_cast<uint4*>(reinterpret_cast<char*>(g_Wtiled) + off) = o;
}

// ---------------------------------------------------------------------------
// Kernel 2: fused gelu + GEMM, occupancy 2. One CTA = (b, t, u-half): M=64,
// 256 threads (2m x 4n warps of 32x32 tiles). TMA bulk W-streaming (zero LSU),
// f32-acc HMMA. Two resident CTAs/SM mutually hide prologue/epilogue/wait
// bubbles on the tensor pipe.
__global__ __launch_bounds__(NTHREADS, 2)
void joiner_kernel(const float* __restrict__ src, const float* __restrict__ tgt,
                   const float* __restrict__ bias, float* __restrict__ out) {
    extern __shared__ char smem[];
    const uint32_t sb = smem_u32(smem);
    const int tid = threadIdx.x;
    const int wid = tid >> 5;
    const int lid = tid & 31;
    const int t = blockIdx.x;
    const int b = blockIdx.y;
    const int mh = blockIdx.z;      // u-half: rows mh*64 .. mh*64+63

    float* src_s = reinterpret_cast<float*>(smem + OFF_SRC);
    float* bias_s = reinterpret_cast<float*>(smem + OFF_BIAS);
    const float* srcrow = src + (size_t)(b * NT + t) * ND;
    src_s[tid] = srcrow[tid];
    src_s[tid + 256] = srcrow[tid + 256];
    bias_s[tid] = bias[tid];
    bias_s[tid + 256] = bias[tid + 256];
    bias_s[tid + 512] = bias[tid + 512];
    bias_s[tid + 768] = bias[tid + 768];

    if (tid == 0) {
#pragma unroll
        for (int s = 0; s < NSTAGE; ++s) MB_INIT(sb + OFF_MBAR + s * 8, 1);
        asm volatile("fence.mbarrier_init.release.cluster;" ::: "memory");
    }
    __syncthreads();   // src_s ready + mbarriers initialized

    // Kick off the first 2 W-tile bulk copies; they overlap the gelu below.
    if (tid == 0) {
#pragma unroll
        for (int g0 = 0; g0 < NSTAGE; ++g0) {
            MB_EXPECT(sb + OFF_MBAR + g0 * 8, BBUF);
            bulk_g2s(sb + OFF_B + g0 * BBUF,
                     reinterpret_cast<const char*>(g_Wtiled) + (size_t)g0 * BBUF,
                     BBUF, sb + OFF_MBAR + g0 * 8);
        }
    }

    // --- A tile: gelu(src + tgt) -> f16 in swizzled SMEM (64 rows x 512) ---
    {
        const int arow = tid >> 2;                 // 0..63 (local u row)
        const int aq = tid & 3;                    // 128-col quarter
        const float* trow = tgt + (size_t)(b * NU + mh * MTILE + arow) * ND + aq * 128;
        const float* srow = src_s + aq * 128;
#pragma unroll
        for (int cc = 0; cc < 128; cc += 8) {
            float4 v0 = *reinterpret_cast<const float4*>(trow + cc);
            float4 v1 = *reinterpret_cast<const float4*>(trow + cc + 4);
            float4 s0 = *reinterpret_cast<const float4*>(srow + cc);
            float4 s1 = *reinterpret_cast<const float4*>(srow + cc + 4);
            __half2 h0 = __floats2half2_rn(gelu_fast(v0.x + s0.x), gelu_fast(v0.y + s0.y));
            __half2 h1 = __floats2half2_rn(gelu_fast(v0.z + s0.z), gelu_fast(v0.w + s0.w));
            __half2 h2 = __floats2half2_rn(gelu_fast(v1.x + s1.x), gelu_fast(v1.y + s1.y));
            __half2 h3 = __floats2half2_rn(gelu_fast(v1.z + s1.z), gelu_fast(v1.w + s1.w));
            uint4 pk;
            pk.x = *reinterpret_cast<uint32_t*>(&h0);
            pk.y = *reinterpret_cast<uint32_t*>(&h1);
            pk.z = *reinterpret_cast<uint32_t*>(&h2);
            pk.w = *reinterpret_cast<uint32_t*>(&h3);
            uint32_t kbyte = (uint32_t)(aq * 128 + cc) * 2;
            *reinterpret_cast<uint4*>(smem + OFF_A + ASW(arow, kbyte)) = pk;
        }
    }
    __syncthreads();   // A tile ready

    // warp tiling: 2 (m) x 4 (n) warps of 32x32 tiles
    const int wm = wid & 1;
    const int wn = wid >> 1;
    const int a_r = (lid & 7) + (((lid >> 3) & 1) << 3);
    const int a_kh = (lid >> 4);
    const int b_n = (lid & 7) + (((lid >> 4) & 1) << 3);
    const int b_kh = ((lid >> 3) & 1);

    float acc[2][4][4];
#pragma unroll
    for (int mt = 0; mt < 2; ++mt)
#pragma unroll
        for (int j = 0; j < 4; ++j)
#pragma unroll
            for (int q = 0; q < 4; ++q) acc[mt][j][q] = 0.0f;

    const size_t rowbase = (size_t)((b * NT + t) * NU + mh * MTILE);

    for (int g = 0; g < GTOT; ++g) {
        const int s = g & 1;
        const int c = g & 7;

        // Wait for stage s fill of this round (phase flips each reuse).
        MB_WAIT(sb + OFF_MBAR + s * 8, (g >> 1) & 1);

        const uint32_t Bbase = sb + OFF_B + s * BBUF;
#pragma unroll
        for (int ks = 0; ks < 4; ++ks) {
            const int k0 = c * KC + ks * 16;
            const uint32_t kb_a = (uint32_t)(k0 + a_kh * 8) * 2;
            uint32_t a0[4], a1[4];
            {
                int r = wm * 32 + a_r;
                ldmatrix_x4(a0[0], a0[1], a0[2], a0[3], sb + OFF_A + ASW(r, kb_a));
                r += 16;
                ldmatrix_x4(a1[0], a1[1], a1[2], a1[3], sb + OFF_A + ASW(r, kb_a));
            }
            const uint32_t kb_b = (uint32_t)(ks * 16 + b_kh * 8) * 2;
            uint32_t bf[8];
            {
                int n = wn * 32 + b_n;
                ldmatrix_x4(bf[0], bf[1], bf[2], bf[3], Bbase + BSW(n, kb_b));
                n += 16;
                ldmatrix_x4(bf[4], bf[5], bf[6], bf[7], Bbase + BSW(n, kb_b));
            }
#pragma unroll
            for (int mt = 0; mt < 2; ++mt) {
                uint32_t* a = mt ? a1 : a0;
#pragma unroll
                for (int j = 0; j < 4; ++j) {
                    mma_16816(acc[mt][j][0], acc[mt][j][1], acc[mt][j][2], acc[mt][j][3],
                              a[0], a[1], a[2], a[3], bf[2 * j], bf[2 * j + 1]);
                }
            }
        }

        // End of an n-subtile: epilogue (hidden by co-resident CTA) + acc reset.
        if (c == 7) {
            const int nbase = (g >> 3) * NSUB;
#pragma unroll
            for (int mt = 0; mt < 2; ++mt) {
                const int r = wm * 32 + mt * 16 + (lid >> 2);
#pragma unroll
                for (int j = 0; j < 4; ++j) {
                    const int col = nbase + wn * 32 + j * 8 + (lid & 3) * 2;
                    const float bi0 = bias_s[col], bi1 = bias_s[col + 1];
                    float2 o0, o1;
                    o0.x = acc[mt][j][0] + bi0;
                    o0.y = acc[mt][j][1] + bi1;
                    o1.x = acc[mt][j][2] + bi0;
                    o1.y = acc[mt][j][3] + bi1;
                    *reinterpret_cast<float2*>(out + (rowbase + r) * NV + col) = o0;
                    *reinterpret_cast<float2*>(out + (rowbase + r + 8) * NV + col) = o1;
                    acc[mt][j][0] = 0.0f; acc[mt][j][1] = 0.0f;
                    acc[mt][j][2] = 0.0f; acc[mt][j][3] = 0.0f;
                }
            }
        }

        // All warps done with stage s -> refill it with chunk g+2.
        __syncthreads();
        if (g + NSTAGE < GTOT && tid == 0) {
            MB_EXPECT(sb + OFF_MBAR + s * 8, BBUF);
            bulk_g2s(sb + OFF_B + s * BBUF,
                     reinterpret_cast<const char*>(g_Wtiled) + (size_t)(g + NSTAGE) * BBUF,
                     BBUF, sb + OFF_MBAR + s * 8);
        }
    }
}

// ---------------------------------------------------------------------------
// Kernel 3: length passthrough tail
__global__ void tail_kernel(const int* __restrict__ sl, const int* __restrict__ tl,
                            float* __restrict__ out, int extra) {
    int i = threadIdx.x;
    if (i < 4 && i < extra) out[i] = (float)sl[i];
    if (i >= 4 && i < 8 && i < extra) out[i] = (float)tl[i - 4];
}

// ---------------------------------------------------------------------------
extern "C" void kernel_launch(void* const* d_in, const int* in_sizes, int n_in,
                              void* d_out, int out_size) {
    const float* src  = (const float*)d_in[0];
    const int*   slen = (const int*)d_in[1];
    const float* tgt  = (const float*)d_in[2];
    const int*   tlen = (const int*)d_in[3];
    const float* W    = (const float*)d_in[4];
    const float* bias = (const float*)d_in[5];
    float* out = (float*)d_out;

    cudaFuncSetAttribute(joiner_kernel, cudaFuncAttributeMaxDynamicSharedMemorySize, SMEM_TOTAL);

    wconv_kernel<<<256, 256>>>(W);

    dim3 grid(NT, NB, 2);  // 4096 CTAs: (t, b, u-half); 2 resident per SM
    joiner_kernel<<<grid, NTHREADS, SMEM_TOTAL>>>(src, tgt, bias, out);

    const long long main_elems = (long long)NB * NT * NU * NV;
    long long extra = (long long)out_size - main_elems;
    if (extra > 0) {
        tail_kernel<<<1, 32>>>(slen, tlen, out + main_elems, (int)extra);
    }
}